// round 2
// baseline (speedup 1.0000x reference)
#include <cuda_runtime.h>

// ---------------- problem constants ----------------
#define NROWS     2048
#define RROWS     4          // batch rows per CTA
#define NTHREADS  512
#define SPONGE_N  1024
#define HALFW     512
#define QUARTW    256
#define ACT_N     256
#define DEPTH_N   8
#define BDEPTH_N  10
#define BF_SIZE   3072
#define BF_HALF   1536
#define BF_QUART  768
#define BF_DEPTH  12
#define PADF      16         // 64B pad at half boundary -> conflict-free LDS.128

#define SP_STRIDE   (SPONGE_N*RROWS + PADF)     // 4112 floats
#define MEM_OFF     (2*SP_STRIDE)               // 8224 floats
#define BF_STRIDE   (BF_SIZE*RROWS + PADF)      // 12304 floats
#define SMEM_FLOATS (2*BF_STRIDE)               // 24608 floats = 98432 B

// ---------------- precomputed tables ----------------
__device__ float2 g_rot  [DEPTH_N*BDEPTH_N*HALFW];  // (cos,sin) sponge butterflies
__device__ float2 g_bfrot[BF_DEPTH*BF_HALF];        // (cos,sin) final butterfly
__device__ float4 g_act  [DEPTH_N*ACT_N];           // (bias, c, t, 1/c)
__device__ int    g_recall[DEPTH_N*ACT_N];
__device__ int    g_outidx[2048];

// Prep: sincos tables + activation constants + index-dtype decode.
__global__ void prep_kernel(const float* __restrict__ angles,
                            const float* __restrict__ bf_angles,
                            const float* __restrict__ act_bias,
                            const float* __restrict__ act_curv,
                            const void*  __restrict__ recall_raw,
                            const void*  __restrict__ out_raw)
{
    int i = blockIdx.x * blockDim.x + threadIdx.x;
    const int NROT = DEPTH_N*BDEPTH_N*HALFW;       // 40960
    const int NBF  = BF_DEPTH*BF_HALF;             // 18432
    if (i < NROT) {
        float s, c; sincosf(angles[i], &s, &c);
        g_rot[i] = make_float2(c, s);
    } else if (i < NROT + NBF) {
        int j = i - NROT;
        float s, c; sincosf(bf_angles[j], &s, &c);
        g_bfrot[j] = make_float2(c, s);
    } else if (i < NROT + NBF + DEPTH_N*ACT_N) {
        int k = i - NROT - NBF;
        float cu = act_curv[k];
        float c  = 0.5f*(cu + sqrtf(cu*cu + 1.0f));
        g_act[k] = make_float4(act_bias[k], c, 0.25f*3.14159265358979323846f/c, 1.0f/c);
    }
    // dtype-robust index decode (int32 vs int64). output_mem_idx is strictly
    // increasing, so if the odd int32 words of the first elements are all zero
    // it must be int64 little-endian.
    if (i < 2048) {
        const int* o32 = (const int*)out_raw;
        bool is64 = (o32[1]==0 && o32[3]==0 && o32[5]==0 && o32[7]==0);
        if (is64) {
            g_outidx[i] = (int)((const long long*)out_raw)[i];
            g_recall[i] = (int)((const long long*)recall_raw)[i];
        } else {
            g_outidx[i] = o32[i];
            g_recall[i] = ((const int*)recall_raw)[i];
        }
    }
}

// ---------------- shared-memory indexing ----------------
__device__ __forceinline__ int idx_s(int p) { return p*RROWS + ((p>>9)<<4); }          // pad at 512
__device__ __forceinline__ int idx_b(int p) { return p*RROWS + ((p>=BF_HALF)?PADF:0); } // pad at 1536

// piecewise activation
__device__ __forceinline__ float actf(float x, float c, float tt, float invc) {
    const float OOS2 = 0.70710678118654752f;   // 1/sqrt(2)
    float r = invc*(OOS2 - __cosf(0.78539816339744831f + c*x));  // mid
    if (x >  tt) r = invc*OOS2 + (x - tt);   // y0 + m0*(x-t), m0=1
    if (x < -tt) r = invc*(OOS2 - 1.0f);     // y1, m1=0
    return r;
}

// y = c*a + s*b (elementwise over 4 rows)
__device__ __forceinline__ float4 rotmix(float c, float s, float4 a, float4 b) {
    float4 y;
    y.x = c*a.x + s*b.x;  y.y = c*a.y + s*b.y;
    y.z = c*a.z + s*b.z;  y.w = c*a.w + s*b.w;
    return y;
}

__global__ void __launch_bounds__(NTHREADS, 2)
sponge_kernel(const float* __restrict__ X,
              const float* __restrict__ scales,
              float* __restrict__ out)
{
    extern __shared__ float sb[];
    const int t    = threadIdx.x;
    const int row0 = blockIdx.x * RROWS;
    float* const MEMB = sb + MEM_OFF;

    // ---- load X * scales into sponge buffer 0, row-minor ----
    {
        float sc0 = scales[t], sc1 = scales[t + HALFW];
        int i0 = idx_s(t), i1 = idx_s(t + HALFW);
        #pragma unroll
        for (int r = 0; r < RROWS; r++) {
            const float* xr = X + (size_t)(row0 + r) * SPONGE_N;
            sb[i0 + r] = xr[t]          * sc0;
            sb[i1 + r] = xr[t + HALFW]  * sc1;
        }
    }
    __syncthreads();

    // ---- per-thread constants for the FUSED 2-layer sponge butterfly ----
    // Layer-pair math: thread t produces z[t], z[t+512] of the second layer.
    //   z[t]     =  co*Y1 + so*Y2            (angle idx t of layer j+1)
    //   z[t+512] = -so*Y1 + co*Y2
    //   Y1 = y[perm(t)]       : angle idx ai1 = t>>1 of layer j
    //   Y2 = y[perm(t)+256]   : angle idx ai2 = ai1+256 of layer j
    // Even t: y = c*x[A] + s*x[B];  odd t: y = c*x[B] - s*x[A]
    // where A = perm(ai), B = A + 256.
    const int  m    = t >> 1;
    const bool odd  = (t & 1);
    const float sgn = odd ? -1.0f : 1.0f;
    const int ai1 = m, ai2 = m + QUARTW;
    const int A1  = (ai1 >> 1) + (ai1 & 1) * HALFW;
    const int A2  = (ai2 >> 1) + (ai2 & 1) * HALFW;
    const int ra1 = idx_s(odd ? A1 + QUARTW : A1);
    const int rb1 = idx_s(odd ? A1          : A1 + QUARTW);
    const int ra2 = idx_s(odd ? A2 + QUARTW : A2);
    const int rb2 = idx_s(odd ? A2          : A2 + QUARTW);
    const int w0  = idx_s(t);
    const int w1  = idx_s(t + HALFW);

    int cur = 0;
    for (int d = 0; d < DEPTH_N; d++) {
        // ---- 10 butterfly layers as 5 fused double-layers ----
        const float2* rotd = g_rot + d*(BDEPTH_N*HALFW);
        #pragma unroll
        for (int s5 = 0; s5 < BDEPTH_N/2; s5++) {
            const float2* r0 = rotd + (2*s5)*HALFW;
            float2 cs1 = r0[ai1];
            float2 cs2 = r0[ai2];
            float2 cso = r0[HALFW + t];          // layer 2s5+1, angle idx t
            const float* IN  = sb + cur*SP_STRIDE;
            float*       OUT = sb + (cur^1)*SP_STRIDE;

            float4 Y1 = rotmix(cs1.x, sgn*cs1.y,
                               *(const float4*)(IN + ra1),
                               *(const float4*)(IN + rb1));
            float4 Y2 = rotmix(cs2.x, sgn*cs2.y,
                               *(const float4*)(IN + ra2),
                               *(const float4*)(IN + rb2));
            *(float4*)(OUT + w0) = rotmix( cso.x, cso.y, Y1, Y2);
            *(float4*)(OUT + w1) = rotmix( cso.x, -cso.y, Y2, Y1);
            cur ^= 1;
            __syncthreads();
        }
        float* S = sb + cur*SP_STRIDE;

        // ---- activation / mem store / recall ----
        int ja = t >> 1;
        float4 ap = g_act[d*ACT_N + ja];          // bias, c, t, 1/c
        float4 x  = *(const float4*)(S + idx_s(HALFW + ja));
        float sg = odd ? -1.0f : 1.0f;
        float4 o;
        o.x = actf(sg*(x.x + ap.x), ap.y, ap.z, ap.w);
        o.y = actf(sg*(x.y + ap.x), ap.y, ap.z, ap.w);
        o.z = actf(sg*(x.z + ap.x), ap.y, ap.z, ap.w);
        o.w = actf(sg*(x.w + ap.x), ap.y, ap.z, ap.w);

        float4 mv = *(const float4*)(S + w0);
        *(float4*)(MEMB + (d*HALFW + t)*RROWS) = mv;   // mem[i*512+t] = sponge[t]

        float4 kv = make_float4(0.f,0.f,0.f,0.f);
        if (t < QUARTW) kv = *(const float4*)(S + idx_s(3*QUARTW + t));
        __syncthreads();

        *(float4*)(S + w0) = o;                        // act_out -> [0,512)
        if (t < QUARTW) {
            *(float4*)(S + idx_s(HALFW + t)) = kv;     // old [768,1024) -> [512,768)
        } else {
            int q  = t - QUARTW;
            int mi = g_recall[d*ACT_N + q];
            *(float4*)(S + idx_s(3*QUARTW + q)) = *(const float4*)(MEMB + mi*RROWS);
        }
        __syncthreads();
    }
    // after 8 depths: 40 flips -> cur == 0, sponge lives in buffer 0

    // ---- build pre = [mem[out_idx] (2048), sponge (1024)] in BF buffer 0 ----
    {
        float4 s0 = *(const float4*)(sb + w0);
        float4 s1 = *(const float4*)(sb + w1);
        __syncthreads();                               // reads done before clobber
        #pragma unroll
        for (int p = 0; p < 2048; p += NTHREADS) {
            int pp = p + t;
            int oi = g_outidx[pp];
            *(float4*)(sb + idx_b(pp)) = *(const float4*)(MEMB + oi*RROWS);
        }
        __syncthreads();                               // mem reads done before clobbering mem head
        *(float4*)(sb + idx_b(2048 + t))         = s0;
        *(float4*)(sb + idx_b(2048 + HALFW + t)) = s1;
        __syncthreads();
    }

    // ---- final 12-layer butterfly on 3072 as 6 fused double-layers ----
    // Same fusion math with HALF=1536, QUART=768. Each thread handles
    // k = t, t+512, t+1024.
    int rba1[3], rbb1[3], rba2[3], rbb2[3], bw0[3], bw1[3], bai1[3], bai2[3], bko[3];
    #pragma unroll
    for (int q = 0; q < 3; q++) {
        int k   = t + q*NTHREADS;
        bool ko = (k & 1);
        int mi  = k >> 1;
        int Ab1 = (mi >> 1) + (mi & 1)*BF_HALF;
        int ai2b = mi + BF_QUART;
        int Ab2 = (ai2b >> 1) + (ai2b & 1)*BF_HALF;
        bai1[q] = mi;  bai2[q] = ai2b;  bko[q] = k;
        rba1[q] = idx_b(ko ? Ab1 + BF_QUART : Ab1);
        rbb1[q] = idx_b(ko ? Ab1           : Ab1 + BF_QUART);
        rba2[q] = idx_b(ko ? Ab2 + BF_QUART : Ab2);
        rbb2[q] = idx_b(ko ? Ab2           : Ab2 + BF_QUART);
        bw0[q]  = idx_b(k);
        bw1[q]  = idx_b(k + BF_HALF);
    }

    int c2 = 0;
    #pragma unroll
    for (int s6 = 0; s6 < BF_DEPTH/2; s6++) {
        const float2* r0 = g_bfrot + (2*s6)*BF_HALF;
        const float* IN  = sb + c2*BF_STRIDE;
        float*       OUT = sb + (c2^1)*BF_STRIDE;
        #pragma unroll
        for (int q = 0; q < 3; q++) {
            float  sg  = (bko[q] & 1) ? -1.0f : 1.0f;
            float2 cs1 = r0[bai1[q]];
            float2 cs2 = r0[bai2[q]];
            float2 cso = r0[BF_HALF + bko[q]];
            float4 Y1 = rotmix(cs1.x, sg*cs1.y,
                               *(const float4*)(IN + rba1[q]),
                               *(const float4*)(IN + rbb1[q]));
            float4 Y2 = rotmix(cs2.x, sg*cs2.y,
                               *(const float4*)(IN + rba2[q]),
                               *(const float4*)(IN + rbb2[q]));
            *(float4*)(OUT + bw0[q]) = rotmix( cso.x, cso.y, Y1, Y2);
            *(float4*)(OUT + bw1[q]) = rotmix( cso.x, -cso.y, Y2, Y1);
        }
        c2 ^= 1;
        __syncthreads();
    }

    // result in buffer 0 (12 layers, even). Emit first 512 columns.
    {
        float4 v = *(const float4*)(sb + idx_b(t));    // t < 512 -> t*4
        out[(size_t)(row0 + 0)*HALFW + t] = v.x;
        out[(size_t)(row0 + 1)*HALFW + t] = v.y;
        out[(size_t)(row0 + 2)*HALFW + t] = v.z;
        out[(size_t)(row0 + 3)*HALFW + t] = v.w;
    }
}

extern "C" void kernel_launch(void* const* d_in, const int* in_sizes, int n_in,
                              void* d_out, int out_size)
{
    (void)in_sizes; (void)n_in; (void)out_size;
    const float* X          = (const float*)d_in[0];
    const float* scales     = (const float*)d_in[1];
    const float* angles     = (const float*)d_in[2];
    const float* act_bias   = (const float*)d_in[3];
    // d_in[4] = act_activation (unused by reference)
    const float* act_curv   = (const float*)d_in[5];
    const float* bf_angles  = (const float*)d_in[6];
    // d_in[7] = shuffle_perm (deterministic riffle, computed inline)
    const void*  recall_raw = d_in[8];
    const void*  out_raw    = d_in[9];
    // d_in[10] = bf_perm (deterministic riffle, computed inline)
    float* out = (float*)d_out;

    const int totalPrep = DEPTH_N*BDEPTH_N*HALFW + BF_DEPTH*BF_HALF + DEPTH_N*ACT_N; // 61440
    prep_kernel<<<(totalPrep + 255)/256, 256>>>(angles, bf_angles, act_bias, act_curv,
                                                recall_raw, out_raw);

    size_t smem = SMEM_FLOATS * sizeof(float);   // 98432 B
    cudaFuncSetAttribute(sponge_kernel, cudaFuncAttributeMaxDynamicSharedMemorySize, (int)smem);
    sponge_kernel<<<NROWS/RROWS, NTHREADS, smem>>>(X, scales, out);
}

// round 3
// speedup vs baseline: 1.3262x; 1.3262x over previous
#include <cuda_runtime.h>

// ---------------- problem constants ----------------
#define NROWS     2048
#define RROWS     4          // batch rows per CTA
#define NTHREADS  512
#define SPONGE_N  1024
#define HALFW     512
#define QUARTW    256
#define ACT_N     256
#define DEPTH_N   8
#define BDEPTH_N  10
#define BF_SIZE   3072
#define BF_HALF   1536
#define BF_QUART  768
#define BF_DEPTH  12

// padded strides: 8-float (2 bank-quad) pad per 256-pos (sponge) / 768-pos (BF) block
#define SP_STRIDE   (SPONGE_N*RROWS + 3*8 + 4)  // idx_s(1023)+4 = 4120
#define MEM_OFF     (2*SP_STRIDE)               // 8240
#define BF_STRIDE   (BF_SIZE*RROWS + 3*8 + 4)   // idx_b(3071)+4 = 12312
#define SMEM_FLOATS (2*BF_STRIDE)               // 24624 floats = 98496 B

// ---------------- precomputed tables ----------------
__device__ float2 g_rot  [DEPTH_N*BDEPTH_N*HALFW];  // (cos,sin) sponge butterflies
__device__ float2 g_bfrot[BF_DEPTH*BF_HALF];        // (cos,sin) final butterfly
__device__ float4 g_act  [DEPTH_N*ACT_N];           // (bias, c, t, 1/c)
__device__ int    g_recall[DEPTH_N*ACT_N];
__device__ int    g_outidx[2048];

// Prep: sincos tables + activation constants + index-dtype decode.
__global__ void prep_kernel(const float* __restrict__ angles,
                            const float* __restrict__ bf_angles,
                            const float* __restrict__ act_bias,
                            const float* __restrict__ act_curv,
                            const void*  __restrict__ recall_raw,
                            const void*  __restrict__ out_raw)
{
    int i = blockIdx.x * blockDim.x + threadIdx.x;
    const int NROT = DEPTH_N*BDEPTH_N*HALFW;       // 40960
    const int NBF  = BF_DEPTH*BF_HALF;             // 18432
    if (i < NROT) {
        float s, c; sincosf(angles[i], &s, &c);
        g_rot[i] = make_float2(c, s);
    } else if (i < NROT + NBF) {
        int j = i - NROT;
        float s, c; sincosf(bf_angles[j], &s, &c);
        g_bfrot[j] = make_float2(c, s);
    } else if (i < NROT + NBF + DEPTH_N*ACT_N) {
        int k = i - NROT - NBF;
        float cu = act_curv[k];
        float c  = 0.5f*(cu + sqrtf(cu*cu + 1.0f));
        g_act[k] = make_float4(act_bias[k], c, 0.25f*3.14159265358979323846f/c, 1.0f/c);
    }
    // dtype-robust index decode (int32 vs int64). output_mem_idx is strictly
    // increasing, so if the odd int32 words of the first elements are all zero
    // it must be int64 little-endian.
    if (i < 2048) {
        const int* o32 = (const int*)out_raw;
        bool is64 = (o32[1]==0 && o32[3]==0 && o32[5]==0 && o32[7]==0);
        if (is64) {
            g_outidx[i] = (int)((const long long*)out_raw)[i];
            g_recall[i] = (int)((const long long*)recall_raw)[i];
        } else {
            g_outidx[i] = o32[i];
            g_recall[i] = ((const int*)recall_raw)[i];
        }
    }
}

// ---------------- shared-memory indexing (conflict-free for fused phases) ----
__device__ __forceinline__ int idx_s(int p) { return p*RROWS + ((p>>8)<<3); }   // +2 quads / 256 pos
__device__ __forceinline__ int idx_b(int p) { return p*RROWS + (p/768)*8;   }   // +2 quads / 768 pos

// piecewise activation
__device__ __forceinline__ float actf(float x, float c, float tt, float invc) {
    const float OOS2 = 0.70710678118654752f;   // 1/sqrt(2)
    float r = invc*(OOS2 - __cosf(0.78539816339744831f + c*x));  // mid
    if (x >  tt) r = invc*OOS2 + (x - tt);   // y0 + m0*(x-t), m0=1
    if (x < -tt) r = invc*(OOS2 - 1.0f);     // y1, m1=0
    return r;
}

// y = c*a + s*b (elementwise over 4 rows)
__device__ __forceinline__ float4 rotmix(float c, float s, float4 a, float4 b) {
    float4 y;
    y.x = c*a.x + s*b.x;  y.y = c*a.y + s*b.y;
    y.z = c*a.z + s*b.z;  y.w = c*a.w + s*b.w;
    return y;
}

__global__ void __launch_bounds__(NTHREADS, 2)
sponge_kernel(const float* __restrict__ X,
              const float* __restrict__ scales,
              float* __restrict__ out)
{
    extern __shared__ float sb[];
    const int t    = threadIdx.x;
    const int row0 = blockIdx.x * RROWS;
    float* const MEMB = sb + MEM_OFF;

    // ---- load X * scales into sponge buffer 0, row-minor ----
    {
        float sc0 = scales[t], sc1 = scales[t + HALFW];
        int i0 = idx_s(t), i1 = idx_s(t + HALFW);
        #pragma unroll
        for (int r = 0; r < RROWS; r++) {
            const float* xr = X + (size_t)(row0 + r) * SPONGE_N;
            sb[i0 + r] = xr[t]          * sc0;
            sb[i1 + r] = xr[t + HALFW]  * sc1;
        }
    }
    __syncthreads();

    // ---- per-thread constants for the FUSED 2-layer sponge butterfly ----
    // thread t produces z[t], z[t+512] of layer j+1:
    //   z[t]     =  co*Y1 + so*Y2 ;  z[t+512] = -so*Y1 + co*Y2
    //   Y1 = y[perm(t)]     (layer-j angle ai1 = t>>1)
    //   Y2 = y[perm(t)+256] (layer-j angle ai2 = ai1+256)
    // even t: y = c*x[A]+s*x[B];  odd t: y = c*x[B]-s*x[A],  A=perm(ai), B=A+256
    const int  m    = t >> 1;
    const bool odd  = (t & 1);
    const float sgn = odd ? -1.0f : 1.0f;
    const int ai1 = m, ai2 = m + QUARTW;
    const int A1  = (ai1 >> 1) + (ai1 & 1) * HALFW;
    const int A2  = (ai2 >> 1) + (ai2 & 1) * HALFW;
    const int ra1 = idx_s(odd ? A1 + QUARTW : A1);
    const int rb1 = idx_s(odd ? A1          : A1 + QUARTW);
    const int ra2 = idx_s(odd ? A2 + QUARTW : A2);
    const int rb2 = idx_s(odd ? A2          : A2 + QUARTW);
    const int w0  = idx_s(t);
    const int w1  = idx_s(t + HALFW);

    int cur = 0;
    for (int d = 0; d < DEPTH_N; d++) {
        // ---- 10 butterfly layers as 5 fused double-layers ----
        const float2* rotd = g_rot + d*(BDEPTH_N*HALFW);
        #pragma unroll
        for (int s5 = 0; s5 < BDEPTH_N/2; s5++) {
            const float2* r0 = rotd + (2*s5)*HALFW;
            float2 cs1 = r0[ai1];
            float2 cs2 = r0[ai2];
            float2 cso = r0[HALFW + t];          // layer 2s5+1, angle idx t
            const float* IN  = sb + cur*SP_STRIDE;
            float*       OUT = sb + (cur^1)*SP_STRIDE;

            float4 Y1 = rotmix(cs1.x, sgn*cs1.y,
                               *(const float4*)(IN + ra1),
                               *(const float4*)(IN + rb1));
            float4 Y2 = rotmix(cs2.x, sgn*cs2.y,
                               *(const float4*)(IN + ra2),
                               *(const float4*)(IN + rb2));
            *(float4*)(OUT + w0) = rotmix( cso.x,  cso.y, Y1, Y2);
            *(float4*)(OUT + w1) = rotmix( cso.x, -cso.y, Y2, Y1);
            cur ^= 1;
            __syncthreads();
        }
        float* S = sb + cur*SP_STRIDE;   // cur back to 0 parity each depth (5 flips alternate)

        // ---- activation / mem store / recall ----
        int ja = t >> 1;
        float4 ap = g_act[d*ACT_N + ja];          // bias, c, t, 1/c
        float4 x  = *(const float4*)(S + idx_s(HALFW + ja));
        float4 o;
        o.x = actf(sgn*(x.x + ap.x), ap.y, ap.z, ap.w);
        o.y = actf(sgn*(x.y + ap.x), ap.y, ap.z, ap.w);
        o.z = actf(sgn*(x.z + ap.x), ap.y, ap.z, ap.w);
        o.w = actf(sgn*(x.w + ap.x), ap.y, ap.z, ap.w);

        float4 mv = *(const float4*)(S + w0);
        *(float4*)(MEMB + (d*HALFW + t)*RROWS) = mv;   // mem[i*512+t] = sponge[t]

        float4 kv = make_float4(0.f,0.f,0.f,0.f);
        if (t < QUARTW) kv = *(const float4*)(S + idx_s(3*QUARTW + t));
        __syncthreads();

        *(float4*)(S + w0) = o;                        // act_out -> [0,512)
        if (t < QUARTW) {
            *(float4*)(S + idx_s(HALFW + t)) = kv;     // old [768,1024) -> [512,768)
        } else {
            int q  = t - QUARTW;
            int mi = g_recall[d*ACT_N + q];
            *(float4*)(S + idx_s(3*QUARTW + q)) = *(const float4*)(MEMB + mi*RROWS);
        }
        __syncthreads();
    }
    // after 8 depths (40 flips): sponge lives in buffer 0

    // ---- build pre = [mem[out_idx] (2048), sponge (1024)] in BF buffer 0 ----
    {
        float4 s0 = *(const float4*)(sb + w0);
        float4 s1 = *(const float4*)(sb + w1);
        __syncthreads();                               // sponge reads done before clobber
        #pragma unroll
        for (int p = 0; p < 2048; p += NTHREADS) {
            int pp = p + t;
            int oi = g_outidx[pp];
            *(float4*)(sb + idx_b(pp)) = *(const float4*)(MEMB + oi*RROWS);
        }
        __syncthreads();                               // mem reads done before clobbering mem head
        *(float4*)(sb + idx_b(2048 + t))         = s0;
        *(float4*)(sb + idx_b(2048 + HALFW + t)) = s1;
        __syncthreads();
    }

    // ---- final 12-layer butterfly on 3072 as 6 fused double-layers ----
    int rba1[3], rbb1[3], rba2[3], rbb2[3], bw0[3], bw1[3], bai1[3], bai2[3];
    float bsg[3];
    #pragma unroll
    for (int q = 0; q < 3; q++) {
        int k   = t + q*NTHREADS;
        bool ko = (k & 1);
        int mi  = k >> 1;
        int Ab1 = (mi >> 1) + (mi & 1)*BF_HALF;
        int a2  = mi + BF_QUART;
        int Ab2 = (a2 >> 1) + (a2 & 1)*BF_HALF;
        bai1[q] = mi;  bai2[q] = a2;  bsg[q] = ko ? -1.0f : 1.0f;
        rba1[q] = idx_b(ko ? Ab1 + BF_QUART : Ab1);
        rbb1[q] = idx_b(ko ? Ab1            : Ab1 + BF_QUART);
        rba2[q] = idx_b(ko ? Ab2 + BF_QUART : Ab2);
        rbb2[q] = idx_b(ko ? Ab2            : Ab2 + BF_QUART);
        bw0[q]  = idx_b(k);
        bw1[q]  = idx_b(k + BF_HALF);
    }

    int c2 = 0;
    #pragma unroll
    for (int s6 = 0; s6 < BF_DEPTH/2; s6++) {
        const float2* r0 = g_bfrot + (2*s6)*BF_HALF;
        const float* IN  = sb + c2*BF_STRIDE;
        float*       OUT = sb + (c2^1)*BF_STRIDE;
        #pragma unroll
        for (int q = 0; q < 3; q++) {
            float2 cs1 = r0[bai1[q]];
            float2 cs2 = r0[bai2[q]];
            float2 cso = r0[BF_HALF + t + q*NTHREADS];
            float4 Y1 = rotmix(cs1.x, bsg[q]*cs1.y,
                               *(const float4*)(IN + rba1[q]),
                               *(const float4*)(IN + rbb1[q]));
            float4 Y2 = rotmix(cs2.x, bsg[q]*cs2.y,
                               *(const float4*)(IN + rba2[q]),
                               *(const float4*)(IN + rbb2[q]));
            *(float4*)(OUT + bw0[q]) = rotmix( cso.x,  cso.y, Y1, Y2);
            *(float4*)(OUT + bw1[q]) = rotmix( cso.x, -cso.y, Y2, Y1);
        }
        c2 ^= 1;
        __syncthreads();
    }

    // result in buffer 0 (12 layers, even). Emit first 512 columns.
    {
        float4 v = *(const float4*)(sb + idx_b(t));
        out[(size_t)(row0 + 0)*HALFW + t] = v.x;
        out[(size_t)(row0 + 1)*HALFW + t] = v.y;
        out[(size_t)(row0 + 2)*HALFW + t] = v.z;
        out[(size_t)(row0 + 3)*HALFW + t] = v.w;
    }
}

extern "C" void kernel_launch(void* const* d_in, const int* in_sizes, int n_in,
                              void* d_out, int out_size)
{
    (void)in_sizes; (void)n_in; (void)out_size;
    const float* X          = (const float*)d_in[0];
    const float* scales     = (const float*)d_in[1];
    const float* angles     = (const float*)d_in[2];
    const float* act_bias   = (const float*)d_in[3];
    // d_in[4] = act_activation (unused by reference)
    const float* act_curv   = (const float*)d_in[5];
    const float* bf_angles  = (const float*)d_in[6];
    // d_in[7] = shuffle_perm (deterministic riffle, computed inline)
    const void*  recall_raw = d_in[8];
    const void*  out_raw    = d_in[9];
    // d_in[10] = bf_perm (deterministic riffle, computed inline)
    float* out = (float*)d_out;

    const int totalPrep = DEPTH_N*BDEPTH_N*HALFW + BF_DEPTH*BF_HALF + DEPTH_N*ACT_N; // 61440
    prep_kernel<<<(totalPrep + 255)/256, 256>>>(angles, bf_angles, act_bias, act_curv,
                                                recall_raw, out_raw);

    size_t smem = SMEM_FLOATS * sizeof(float);   // 98496 B
    cudaFuncSetAttribute(sponge_kernel, cudaFuncAttributeMaxDynamicSharedMemorySize, (int)smem);
    sponge_kernel<<<NROWS/RROWS, NTHREADS, smem>>>(X, scales, out);
}

// round 5
// speedup vs baseline: 1.5143x; 1.1419x over previous
#include <cuda_runtime.h>

// ---------------- problem constants ----------------
#define NROWS     2048
#define RROWS     4          // batch rows per CTA (split 2+2 across thread row-halves)
#define NTHREADS  512
#define SPONGE_N  1024
#define HALFW     512
#define QUARTW    256
#define ACT_N     256
#define DEPTH_N   8
#define BDEPTH_N  10
#define BF_SIZE   3072
#define BF_HALF   1536
#define BF_QUART  768
#define BF_DEPTH  12

// strides for the padded layouts (see isp/ibf)
#define SP_STRIDE   4624                 // >= isp(1023)+4, 16B aligned
#define MEM_OFF     (2*SP_STRIDE)        // 9248
#define BF_STRIDE   13840                // >= ibf(3071)+4
#define SMEM_FLOATS (2*BF_STRIDE)        // 27680 floats = 110720 B (2 CTAs/SM fits 228KB)

// ---------------- precomputed tables ----------------
__device__ __align__(16) float2 g_rot  [DEPTH_N*BDEPTH_N*HALFW];  // sponge (cos,sin)
__device__ __align__(16) float2 g_bfrot[BF_DEPTH*BF_HALF];        // final  (cos,sin)
__device__ float4 g_act  [DEPTH_N*ACT_N];           // (bias, c, t, 1/c)
__device__ int    g_recall[DEPTH_N*ACT_N];
__device__ int    g_outidx[2048];

__global__ void prep_kernel(const float* __restrict__ angles,
                            const float* __restrict__ bf_angles,
                            const float* __restrict__ act_bias,
                            const float* __restrict__ act_curv,
                            const void*  __restrict__ recall_raw,
                            const void*  __restrict__ out_raw)
{
    int i = blockIdx.x * blockDim.x + threadIdx.x;
    const int NROT = DEPTH_N*BDEPTH_N*HALFW;       // 40960
    const int NBF  = BF_DEPTH*BF_HALF;             // 18432
    if (i < NROT) {
        float s, c; sincosf(angles[i], &s, &c);
        g_rot[i] = make_float2(c, s);
    } else if (i < NROT + NBF) {
        int j = i - NROT;
        float s, c; sincosf(bf_angles[j], &s, &c);
        g_bfrot[j] = make_float2(c, s);
    } else if (i < NROT + NBF + DEPTH_N*ACT_N) {
        int k = i - NROT - NBF;
        float cu = act_curv[k];
        float c  = 0.5f*(cu + sqrtf(cu*cu + 1.0f));
        g_act[k] = make_float4(act_bias[k], c, 0.25f*3.14159265358979323846f/c, 1.0f/c);
    }
    // dtype-robust index decode (int32 vs int64)
    if (i < 2048) {
        const int* o32 = (const int*)out_raw;
        bool is64 = (o32[1]==0 && o32[3]==0 && o32[5]==0 && o32[7]==0);
        if (is64) {
            g_outidx[i] = (int)((const long long*)out_raw)[i];
            g_recall[i] = (int)((const long long*)recall_raw)[i];
        } else {
            g_outidx[i] = o32[i];
            g_recall[i] = ((const int*)recall_raw)[i];
        }
    }
}

// ---------------- padded shared-memory indexing (rh=0 base; rows [0..3] at +0..+3) ----
__device__ __forceinline__ int isp(int p) { return 4*p + ((p>>3)<<2) + ((p>>9)<<4); }
__device__ __forceinline__ int ibf(int p) { return 4*p + ((p>>3)<<2) + ((p>=1536)?16:0); }

// fixed offsets (constant across all valid base positions; re-derived & checked)
#define SR1 576      // isp(A+128)-isp(A),  A in [0,128)u[512,640)
#define SR2 1152     // +256
#define SR3 1728     // +384
#define SW1 4        // isp(2m+1)-isp(2m)
#define SW2 2320     // isp(2m+512)-isp(2m)
#define SW3 2324
#define BR1 1728     // ibf(A+384)-ibf(A),  A in [0,384)u[1536,1920)
#define BR2 3456     // +768
#define BR3 5184     // +1152
#define BW1 4
#define BW2 6928     // ibf(2p'+1536)-ibf(2p')
#define BW3 6932

// piecewise activation
__device__ __forceinline__ float actf(float x, float c, float tt, float invc) {
    const float OOS2 = 0.70710678118654752f;
    float r = invc*(OOS2 - __cosf(0.78539816339744831f + c*x));
    if (x >  tt) r = invc*OOS2 + (x - tt);
    if (x < -tt) r = invc*(OOS2 - 1.0f);
    return r;
}

__device__ __forceinline__ float2 mix2(float c, float s, float2 a, float2 b) {
    return make_float2(c*a.x + s*b.x, c*a.y + s*b.y);
}

__global__ void __launch_bounds__(NTHREADS, 2)
sponge_kernel(const float* __restrict__ X,
              const float* __restrict__ scales,
              float* __restrict__ out)
{
    extern __shared__ float sb[];
    const int t    = threadIdx.x;
    const int row0 = blockIdx.x * RROWS;
    float* const MEMB = sb + MEM_OFF;

    // ---- load X * scales into sponge buffer 0 ----
    {
        float sc0 = scales[t], sc1 = scales[t + HALFW];
        int i0 = isp(t), i1 = i0 + SW2;   // isp(t+512)
        #pragma unroll
        for (int r = 0; r < RROWS; r++) {
            const float* xr = X + (size_t)(row0 + r) * SPONGE_N;
            sb[i0 + r] = xr[t]         * sc0;
            sb[i1 + r] = xr[t + HALFW] * sc1;
        }
    }
    __syncthreads();

    // ---- per-thread constants: thread = (pair m, row-half rh) ----
    // produces all 4 outputs {2m, 2m+1, 2m+512, 2m+513} (2 rows each),
    // from inputs {A, A+128, A+256, A+384}, A = perm(m) = (m>>1)+(m&1)*512.
    const int  m   = t >> 1;
    const int  rh  = t & 1;
    const bool odd = rh;
    const int  A1  = (m >> 1) + (m & 1) * HALFW;
    const int  rb  = isp(A1)   + 2*rh;   // read base (float2)
    const int  wb  = isp(2*m)  + 2*rh;   // write base (float2)
    const int  w0  = isp(t);             // float4 addrs for act phase
    const int  w1  = w0 + SW2;           // isp(t+512)

    int cur = 0;
    for (int d = 0; d < DEPTH_N; d++) {
        const float2* rotd = g_rot + d*(BDEPTH_N*HALFW);
        #pragma unroll
        for (int s5 = 0; s5 < BDEPTH_N/2; s5++) {
            const float2* r0 = rotd + (2*s5)*HALFW;
            float2 cs1 = r0[m];
            float2 cs2 = r0[m + QUARTW];
            float4 co4 = ((const float4*)(rotd + (2*s5+1)*HALFW))[m]; // angles 2m,2m+1
            const float* IN  = sb + cur*SP_STRIDE;
            float*       OUT = sb + (cur^1)*SP_STRIDE;

            float2 a1 = *(const float2*)(IN + rb);
            float2 a2 = *(const float2*)(IN + rb + SR1);
            float2 b1 = *(const float2*)(IN + rb + SR2);
            float2 b2 = *(const float2*)(IN + rb + SR3);
            // layer j: pairs m and m+256
            float2 y1e = mix2(cs1.x,  cs1.y, a1, b1);   // y[m]
            float2 y1o = mix2(cs1.x, -cs1.y, b1, a1);   // y[m+512]
            float2 y2e = mix2(cs2.x,  cs2.y, a2, b2);   // y[m+256]
            float2 y2o = mix2(cs2.x, -cs2.y, b2, a2);   // y[m+768]
            // layer j+1
            *(float2*)(OUT + wb)       = mix2(co4.x,  co4.y, y1e, y2e);  // z[2m]
            *(float2*)(OUT + wb + SW1) = mix2(co4.z,  co4.w, y1o, y2o);  // z[2m+1]
            *(float2*)(OUT + wb + SW2) = mix2(co4.x, -co4.y, y2e, y1e);  // z[2m+512]
            *(float2*)(OUT + wb + SW3) = mix2(co4.z, -co4.w, y2o, y1o);  // z[2m+513]
            cur ^= 1;
            __syncthreads();
        }
        float* S = sb + cur*SP_STRIDE;

        // ---- activation / mem store / recall (float4, rows 0..3) ----
        int ja = t >> 1;
        float4 ap = g_act[d*ACT_N + ja];
        float4 x  = *(const float4*)(S + isp(HALFW + ja));
        float sg  = odd ? -1.0f : 1.0f;
        float4 o;
        o.x = actf(sg*(x.x + ap.x), ap.y, ap.z, ap.w);
        o.y = actf(sg*(x.y + ap.x), ap.y, ap.z, ap.w);
        o.z = actf(sg*(x.z + ap.x), ap.y, ap.z, ap.w);
        o.w = actf(sg*(x.w + ap.x), ap.y, ap.z, ap.w);

        float4 mv = *(const float4*)(S + w0);
        *(float4*)(MEMB + (d*HALFW + t)*RROWS) = mv;

        float4 kv = make_float4(0.f,0.f,0.f,0.f);
        if (t < QUARTW) kv = *(const float4*)(S + isp(3*QUARTW + t));
        __syncthreads();

        *(float4*)(S + w0) = o;
        if (t < QUARTW) {
            *(float4*)(S + isp(HALFW + t)) = kv;
        } else {
            int q  = t - QUARTW;
            int mi = g_recall[d*ACT_N + q];
            *(float4*)(S + isp(3*QUARTW + q)) = *(const float4*)(MEMB + mi*RROWS);
        }
        __syncthreads();
    }
    // after 8 depths (40 flips): sponge in buffer 0

    // ---- build pre = [mem[out_idx] (2048), sponge (1024)] in BF buffer 0 ----
    // ibf(2047)+4 = 9228 <= MEM_OFF, so the first loop never clobbers MEMB;
    // the tail writes (>= ibf(2048) = 9232) overlap MEMB but only after the sync.
    {
        float4 s0 = *(const float4*)(sb + w0);
        float4 s1 = *(const float4*)(sb + w1);
        __syncthreads();
        #pragma unroll
        for (int p = 0; p < 2048; p += NTHREADS) {
            int pp = p + t;
            int oi = g_outidx[pp];
            *(float4*)(sb + ibf(pp)) = *(const float4*)(MEMB + oi*RROWS);
        }
        __syncthreads();
        *(float4*)(sb + ibf(2048 + t))         = s0;
        *(float4*)(sb + ibf(2048 + HALFW + t)) = s1;
        __syncthreads();
    }

    // ---- final 12-layer butterfly on 3072 as 6 fused double-layers ----
    // 768 thread-pairs: slot j2 handles pair p' = m + 256*j2, j2 in [0,3).
    // Outputs {2p', 2p'+1, 2p'+1536, 2p'+1537}; reads {A,A+384,A+768,A+1152},
    // A = perm(p') in [0,384) u [1536,1920)  (max read pos = 3071).
    int rbB[3], wbB[3];
    #pragma unroll
    for (int j2 = 0; j2 < 3; j2++) {
        int pp  = m + 256*j2;
        int Ab  = (pp >> 1) + (pp & 1)*BF_HALF;
        rbB[j2] = ibf(Ab)    + 2*rh;
        wbB[j2] = ibf(2*pp)  + 2*rh;
    }

    int c2 = 0;
    for (int s6 = 0; s6 < BF_DEPTH/2; s6++) {
        const float2* r0 = g_bfrot + (2*s6)*BF_HALF;
        const float4* r1 = (const float4*)(g_bfrot + (2*s6+1)*BF_HALF);
        const float* IN  = sb + c2*BF_STRIDE;
        float*       OUT = sb + (c2^1)*BF_STRIDE;
        #pragma unroll
        for (int j2 = 0; j2 < 3; j2++) {
            int pp = m + 256*j2;
            float2 cs1 = r0[pp];
            float2 cs2 = r0[pp + BF_QUART];
            float4 co4 = r1[pp];                 // angles 2pp, 2pp+1
            int rbs = rbB[j2], wbs = wbB[j2];

            float2 a1 = *(const float2*)(IN + rbs);
            float2 a2 = *(const float2*)(IN + rbs + BR1);
            float2 b1 = *(const float2*)(IN + rbs + BR2);
            float2 b2 = *(const float2*)(IN + rbs + BR3);
            float2 y1e = mix2(cs1.x,  cs1.y, a1, b1);   // y[pp]
            float2 y1o = mix2(cs1.x, -cs1.y, b1, a1);   // y[pp+1536]
            float2 y2e = mix2(cs2.x,  cs2.y, a2, b2);   // y[pp+768]
            float2 y2o = mix2(cs2.x, -cs2.y, b2, a2);   // y[pp+2304]
            *(float2*)(OUT + wbs)       = mix2(co4.x,  co4.y, y1e, y2e); // z[2pp]
            *(float2*)(OUT + wbs + BW1) = mix2(co4.z,  co4.w, y1o, y2o); // z[2pp+1]
            *(float2*)(OUT + wbs + BW2) = mix2(co4.x, -co4.y, y2e, y1e); // z[2pp+1536]
            *(float2*)(OUT + wbs + BW3) = mix2(co4.z, -co4.w, y2o, y1o); // z[2pp+1537]
        }
        c2 ^= 1;
        __syncthreads();
    }

    // result in buffer 0; emit first 512 columns
    {
        float4 v = *(const float4*)(sb + ibf(t));
        out[(size_t)(row0 + 0)*HALFW + t] = v.x;
        out[(size_t)(row0 + 1)*HALFW + t] = v.y;
        out[(size_t)(row0 + 2)*HALFW + t] = v.z;
        out[(size_t)(row0 + 3)*HALFW + t] = v.w;
    }
}

extern "C" void kernel_launch(void* const* d_in, const int* in_sizes, int n_in,
                              void* d_out, int out_size)
{
    (void)in_sizes; (void)n_in; (void)out_size;
    const float* X          = (const float*)d_in[0];
    const float* scales     = (const float*)d_in[1];
    const float* angles     = (const float*)d_in[2];
    const float* act_bias   = (const float*)d_in[3];
    // d_in[4] = act_activation (unused by reference)
    const float* act_curv   = (const float*)d_in[5];
    const float* bf_angles  = (const float*)d_in[6];
    // d_in[7] = shuffle_perm (deterministic riffle, computed inline)
    const void*  recall_raw = d_in[8];
    const void*  out_raw    = d_in[9];
    // d_in[10] = bf_perm (deterministic riffle, computed inline)
    float* out = (float*)d_out;

    const int totalPrep = DEPTH_N*BDEPTH_N*HALFW + BF_DEPTH*BF_HALF + DEPTH_N*ACT_N;
    prep_kernel<<<(totalPrep + 255)/256, 256>>>(angles, bf_angles, act_bias, act_curv,
                                                recall_raw, out_raw);

    size_t smem = SMEM_FLOATS * sizeof(float);   // 110720 B
    cudaFuncSetAttribute(sponge_kernel, cudaFuncAttributeMaxDynamicSharedMemorySize, (int)smem);
    sponge_kernel<<<NROWS/RROWS, NTHREADS, smem>>>(X, scales, out);
}